// round 7
// baseline (speedup 1.0000x reference)
#include <cuda_runtime.h>
#include <math.h>
#include <stdint.h>

#define BB 4
#define SS 2048
#define DD 768
#define HH 12
#define DKK 64
#define MTOT (BB*SS)   // 8192
#define NQKV (3*DD)    // 2304

// Scratch (all values stored as tf32-rounded fp32 bit patterns)
__device__ float g_qkv[(size_t)3 * BB * HH * SS * DKK];
__device__ float g_obuf[(size_t)BB * SS * DD];
__device__ float g_xr[(size_t)MTOT * DD];
__device__ float g_wqkvr[(size_t)NQKV * DD];
__device__ float g_wor[(size_t)DD * DD];

// ---------------------------------------------------------------------------
// helpers
// ---------------------------------------------------------------------------
__device__ __forceinline__ uint32_t f2tf(float x) {
    uint32_t r;
    asm("cvt.rna.tf32.f32 %0, %1;" : "=r"(r) : "f"(x));
    return r;
}

__device__ __forceinline__ void mma_tf32(float* c, const uint32_t* a, const uint32_t* b) {
    asm volatile(
        "mma.sync.aligned.m16n8k8.row.col.f32.tf32.tf32.f32 "
        "{%0,%1,%2,%3}, {%4,%5,%6,%7}, {%8,%9}, {%0,%1,%2,%3};\n"
        : "+f"(c[0]), "+f"(c[1]), "+f"(c[2]), "+f"(c[3])
        : "r"(a[0]), "r"(a[1]), "r"(a[2]), "r"(a[3]), "r"(b[0]), "r"(b[1]));
}

__device__ __forceinline__ void cp_async16(void* smem, const void* gmem) {
    uint32_t s = (uint32_t)__cvta_generic_to_shared(smem);
    asm volatile("cp.async.cg.shared.global [%0], [%1], 16;\n" :: "r"(s), "l"(gmem));
}
__device__ __forceinline__ void cp_commit() { asm volatile("cp.async.commit_group;\n"); }
template <int N>
__device__ __forceinline__ void cp_wait() { asm volatile("cp.async.wait_group %0;\n" :: "n"(N)); }

// fast 2^x on the FMA/ALU pipes (no MUFU).
__device__ __forceinline__ float fexp2(float x) {
    x = fmaxf(x, -120.0f);
    float z = x + 12582912.0f;
    float f = x - (z - 12582912.0f);
    int   i = __float_as_int(z) - 0x4B400000;
    float p = 0.0096818f;
    p = fmaf(p, f, 0.0555041f);
    p = fmaf(p, f, 0.2402265f);
    p = fmaf(p, f, 0.6931472f);
    p = fmaf(p, f, 1.0f);
    return __int_as_float(__float_as_int(p) + (i << 23));
}

#define CEXP 0.1803368801111204f   /* log2(e)/sqrt(64) */
#define NEGINF __int_as_float(0xff800000)

// ---------------------------------------------------------------------------
// tf32 pre-rounding pass
// ---------------------------------------------------------------------------
__global__ void preround(float* __restrict__ dst, const float* __restrict__ src, int n4) {
    int i = blockIdx.x * blockDim.x + threadIdx.x;
    if (i < n4) {
        float4 v = ((const float4*)src)[i];
        uint4 u;
        u.x = f2tf(v.x); u.y = f2tf(v.y); u.z = f2tf(v.z); u.w = f2tf(v.w);
        ((uint4*)dst)[i] = u;
    }
}

// ---------------------------------------------------------------------------
// tf32 tensor-core GEMM on PRE-ROUNDED inputs: C = A(M,K) @ W(N,K)^T.
// BM=256, BN=128, BK=16; 8 warps (4x2), warp 64x64. 3-stage cp.async.
// ---------------------------------------------------------------------------
#define GSTAGES 3
#define GASLOT (256 * 20)
#define GBSLOT (128 * 20)
#define GEMM_SMEM (GSTAGES * (GASLOT + GBSLOT) * 4)

template <int REMAP>
__global__ __launch_bounds__(256, 1) void gemm_tf32(const float* __restrict__ A,
                                                    const float* __restrict__ W,
                                                    float* __restrict__ C,
                                                    int M, int N, int K) {
    extern __shared__ uint32_t gsm[];
    uint32_t* As = gsm;
    uint32_t* Bs = gsm + GSTAGES * GASLOT;

    const int tid  = threadIdx.x;
    const int lane = tid & 31;
    const int wid  = tid >> 5;
    const int wm   = wid >> 1;
    const int wn   = wid & 1;
    const int m0   = blockIdx.y * 256;
    const int n0   = blockIdx.x * 128;

    const int r0 = tid >> 2;
    const int kv = (tid & 3) << 2;

    const int NT = K / 16;

    const float* Abase = A + (size_t)(m0 + r0) * K + kv;
    const float* Wbase = W + (size_t)(n0 + r0) * K + kv;

    float c[4][8][4];
#pragma unroll
    for (int mt = 0; mt < 4; mt++)
#pragma unroll
        for (int nt = 0; nt < 8; nt++)
#pragma unroll
            for (int j = 0; j < 4; j++) c[mt][nt][j] = 0.0f;

#pragma unroll
    for (int s = 0; s < GSTAGES - 1; s++) {
        uint32_t* as = As + s * GASLOT;
        uint32_t* bs = Bs + s * GBSLOT;
        const float* ap = Abase + s * 16;
        const float* wp = Wbase + s * 16;
#pragma unroll
        for (int rr = 0; rr < 4; rr++)
            cp_async16(&as[(r0 + rr * 64) * 20 + kv], ap + (size_t)(rr * 64) * K);
        cp_async16(&bs[r0 * 20 + kv], wp);
        cp_async16(&bs[(r0 + 64) * 20 + kv], wp + (size_t)64 * K);
        cp_commit();
    }

    for (int kt = 0; kt < NT; kt++) {
        cp_wait<GSTAGES - 2>();
        __syncthreads();

        if (kt + GSTAGES - 1 < NT) {
            const int slot = (kt + GSTAGES - 1) % GSTAGES;
            uint32_t* as = As + slot * GASLOT;
            uint32_t* bs = Bs + slot * GBSLOT;
            const float* ap = Abase + (size_t)(kt + GSTAGES - 1) * 16;
            const float* wp = Wbase + (size_t)(kt + GSTAGES - 1) * 16;
#pragma unroll
            for (int rr = 0; rr < 4; rr++)
                cp_async16(&as[(r0 + rr * 64) * 20 + kv], ap + (size_t)(rr * 64) * K);
            cp_async16(&bs[r0 * 20 + kv], wp);
            cp_async16(&bs[(r0 + 64) * 20 + kv], wp + (size_t)64 * K);
        }
        cp_commit();

        const uint32_t* as = As + (kt % GSTAGES) * GASLOT;
        const uint32_t* bs = Bs + (kt % GSTAGES) * GBSLOT;

#pragma unroll
        for (int k0 = 0; k0 < 16; k0 += 8) {
            uint32_t af[4][4];
#pragma unroll
            for (int mt = 0; mt < 4; mt++) {
                const int row = wm * 64 + mt * 16 + (lane >> 2);
                af[mt][0] = as[row * 20 + k0 + (lane & 3)];
                af[mt][1] = as[(row + 8) * 20 + k0 + (lane & 3)];
                af[mt][2] = as[row * 20 + k0 + 4 + (lane & 3)];
                af[mt][3] = as[(row + 8) * 20 + k0 + 4 + (lane & 3)];
            }
            uint32_t bf[8][2];
#pragma unroll
            for (int nt = 0; nt < 8; nt++) {
                const int col = wn * 64 + nt * 8 + (lane >> 2);
                bf[nt][0] = bs[col * 20 + k0 + (lane & 3)];
                bf[nt][1] = bs[col * 20 + k0 + 4 + (lane & 3)];
            }
#pragma unroll
            for (int mt = 0; mt < 4; mt++)
#pragma unroll
                for (int nt = 0; nt < 8; nt++)
                    mma_tf32(c[mt][nt], af[mt], bf[nt]);
        }
    }

    // epilogue
#pragma unroll
    for (int mt = 0; mt < 4; mt++) {
#pragma unroll
        for (int half = 0; half < 2; half++) {
            const int m = m0 + wm * 64 + mt * 16 + (lane >> 2) + half * 8;
#pragma unroll
            for (int nt = 0; nt < 8; nt++) {
                const int n = n0 + wn * 64 + nt * 8 + 2 * (lane & 3);
                const float v0 = c[mt][nt][2 * half + 0];
                const float v1 = c[mt][nt][2 * half + 1];
                if (REMAP) {
                    // n,n+1 are consecutive dk within one head -> float2 store
                    const int t = (n >= 2 * DD) ? 2 : ((n >= DD) ? 1 : 0);
                    const int r = n - t * DD;
                    const int hh = r >> 6;
                    const int e = r & 63;
                    const int bb = m >> 11;
                    const int ss = m & 2047;
                    size_t idx = ((((size_t)t * BB + bb) * HH + hh) * SS + ss) * DKK + e;
                    uint2 u;
                    u.x = f2tf(v0);
                    u.y = f2tf(v1);
                    *(uint2*)&g_qkv[idx] = u;
                } else {
                    float2 v = make_float2(v0, v1);
                    *(float2*)&C[(size_t)m * N + n] = v;
                }
            }
        }
    }
}

// ---------------------------------------------------------------------------
// Tensor-core causal flash attention. Br=128, Bc=64, dk=64.
// 128 threads = 4 warps; warp tile 32x64. Q fragments in REGISTERS.
// Double-buffered K/V via cp.async issued one full iteration ahead.
// ONE __syncthreads per k-iteration (P tile is warp-private -> __syncwarp).
// smem: Ks[2] + Vs[2] (4 x 64x68) + Ps 128x68 (Q staging) = 104448 B.
// ---------------------------------------------------------------------------
__global__ __launch_bounds__(128, 2) void attn_tc() {
    extern __shared__ uint32_t smx[];
    uint32_t* Kbuf[2] = { smx,            smx + 4352     };
    uint32_t* Vbuf[2] = { smx + 2 * 4352, smx + 3 * 4352 };
    uint32_t* Ps      =   smx + 4 * 4352;   // [128][68], Q staging first

    const int qt = (SS / 128 - 1) - blockIdx.x;   // largest work first
    const int h  = blockIdx.y;
    const int b  = blockIdx.z;
    const int tid  = threadIdx.x;
    const int lane = tid & 31;
    const int wm   = tid >> 5;   // 0..3 -> 32-row slice

    const size_t plane = (size_t)BB * HH * SS * DKK;
    const size_t bh = (size_t)b * HH + h;
    const float* Qg = g_qkv + 0 * plane + bh * SS * DKK;
    const float* Kg = g_qkv + 1 * plane + bh * SS * DKK;
    const float* Vg = g_qkv + 2 * plane + bh * SS * DKK;

    const int lrow = tid >> 4;           // 0..7
    const int lc4  = (tid & 15) << 2;    // col*4

    // stage Q into Ps (group 1), then K0+V0 (group 2)
#pragma unroll
    for (int i = 0; i < 16; i++) {
        const int row = lrow + i * 8;
        cp_async16(&Ps[row * 68 + lc4], Qg + ((size_t)(qt * 128 + row) << 6) + lc4);
    }
    cp_commit();
#pragma unroll
    for (int i = 0; i < 8; i++) {
        const int row = lrow + i * 8;
        cp_async16(&Kbuf[0][row * 68 + lc4], Kg + ((size_t)row << 6) + lc4);
        cp_async16(&Vbuf[0][row * 68 + lc4], Vg + ((size_t)row << 6) + lc4);
    }
    cp_commit();

    cp_wait<1>();      // Q staged
    __syncthreads();

    // Q fragments -> registers (loop-invariant)
    uint32_t qf[8][2][4];
#pragma unroll
    for (int k0c = 0; k0c < 8; k0c++) {
        const int k0 = k0c * 8;
#pragma unroll
        for (int mt = 0; mt < 2; mt++) {
            const int row = wm * 32 + mt * 16 + (lane >> 2);
            qf[k0c][mt][0] = Ps[row * 68 + k0 + (lane & 3)];
            qf[k0c][mt][1] = Ps[(row + 8) * 68 + k0 + (lane & 3)];
            qf[k0c][mt][2] = Ps[row * 68 + k0 + 4 + (lane & 3)];
            qf[k0c][mt][3] = Ps[(row + 8) * 68 + k0 + 4 + (lane & 3)];
        }
    }
    __syncthreads();   // everyone done reading Ps before it becomes the P tile

    float m_run[4], l_run[4], o[2][8][4];
#pragma unroll
    for (int r = 0; r < 4; r++) { m_run[r] = NEGINF; l_run[r] = 0.0f; }
#pragma unroll
    for (int mt = 0; mt < 2; mt++)
#pragma unroll
        for (int nt = 0; nt < 8; nt++)
#pragma unroll
            for (int j = 0; j < 4; j++) o[mt][nt][j] = 0.0f;

    const int ktmax = 2 * qt + 1;
    for (int kt = 0; kt <= ktmax; kt++) {
        cp_wait<0>();       // K(kt)+V(kt) landed (issued a full iteration ago)
        __syncthreads();    // visible to all warps; prev iter's buffer reads done

        // issue K(kt+1)/V(kt+1) into the other buffer (read two iters ago)
        if (kt < ktmax) {
            uint32_t* kn = Kbuf[(kt + 1) & 1];
            uint32_t* vn = Vbuf[(kt + 1) & 1];
#pragma unroll
            for (int i = 0; i < 8; i++) {
                const int row = lrow + i * 8;
                cp_async16(&kn[row * 68 + lc4],
                           Kg + ((size_t)((kt + 1) * 64 + row) << 6) + lc4);
                cp_async16(&vn[row * 68 + lc4],
                           Vg + ((size_t)((kt + 1) * 64 + row) << 6) + lc4);
            }
            cp_commit();
        }

        const uint32_t* Ks = Kbuf[kt & 1];
        const uint32_t* Vs = Vbuf[kt & 1];

        // S = Q K^T : warp computes 32 x 64 (Q from registers)
        float s[2][8][4];
#pragma unroll
        for (int mt = 0; mt < 2; mt++)
#pragma unroll
            for (int nt = 0; nt < 8; nt++)
#pragma unroll
                for (int j = 0; j < 4; j++) s[mt][nt][j] = 0.0f;

#pragma unroll
        for (int k0c = 0; k0c < 8; k0c++) {
            const int k0 = k0c * 8;
            uint32_t bf[8][2];
#pragma unroll
            for (int nt = 0; nt < 8; nt++) {
                const int col = nt * 8 + (lane >> 2);
                bf[nt][0] = Ks[col * 68 + k0 + (lane & 3)];
                bf[nt][1] = Ks[col * 68 + k0 + 4 + (lane & 3)];
            }
#pragma unroll
            for (int mt = 0; mt < 2; mt++)
#pragma unroll
                for (int nt = 0; nt < 8; nt++)
                    mma_tf32(s[mt][nt], qf[k0c][mt], bf[nt]);
        }

        // causal mask (only diagonal-adjacent tiles)
        if (kt >= 2 * qt) {
#pragma unroll
            for (int mt = 0; mt < 2; mt++)
#pragma unroll
                for (int cc = 0; cc < 4; cc++) {
                    const int row_g = qt * 128 + wm * 32 + mt * 16 + (lane >> 2) + 8 * (cc >> 1);
#pragma unroll
                    for (int nt = 0; nt < 8; nt++) {
                        const int col_g = kt * 64 + nt * 8 + 2 * (lane & 3) + (cc & 1);
                        if (col_g > row_g) s[mt][nt][cc] = NEGINF;
                    }
                }
        }

        // online softmax (intra-warp quad reduction; warp owns full rows)
#pragma unroll
        for (int mt = 0; mt < 2; mt++)
#pragma unroll
            for (int half = 0; half < 2; half++) {
                const int rid = mt * 2 + half;
                float mv = NEGINF;
#pragma unroll
                for (int nt = 0; nt < 8; nt++)
                    mv = fmaxf(mv, fmaxf(s[mt][nt][2 * half], s[mt][nt][2 * half + 1]));
                mv = fmaxf(mv, __shfl_xor_sync(0xffffffffu, mv, 1));
                mv = fmaxf(mv, __shfl_xor_sync(0xffffffffu, mv, 2));
                const float mn = fmaxf(m_run[rid], mv);
                const float sc = fexp2((m_run[rid] - mn) * CEXP);
                m_run[rid] = mn;
                float rs = 0.0f;
#pragma unroll
                for (int nt = 0; nt < 8; nt++)
#pragma unroll
                    for (int j = 0; j < 2; j++) {
                        float p = fexp2((s[mt][nt][2 * half + j] - mn) * CEXP);
                        s[mt][nt][2 * half + j] = p;
                        rs += p;
                    }
                rs += __shfl_xor_sync(0xffffffffu, rs, 1);
                rs += __shfl_xor_sync(0xffffffffu, rs, 2);
                l_run[rid] = l_run[rid] * sc + rs;
#pragma unroll
                for (int nt = 0; nt < 8; nt++)
#pragma unroll
                    for (int j = 0; j < 2; j++) o[mt][nt][2 * half + j] *= sc;
            }

        // write P (tf32-rounded) to warp-private smem rows
#pragma unroll
        for (int mt = 0; mt < 2; mt++)
#pragma unroll
            for (int half = 0; half < 2; half++) {
                const int row = wm * 32 + mt * 16 + (lane >> 2) + 8 * half;
#pragma unroll
                for (int nt = 0; nt < 8; nt++) {
                    const int col = nt * 8 + 2 * (lane & 3);
                    uint2 u;
                    u.x = f2tf(s[mt][nt][2 * half]);
                    u.y = f2tf(s[mt][nt][2 * half + 1]);
                    *(uint2*)&Ps[row * 68 + col] = u;
                }
            }
        __syncwarp();   // P rows are warp-private: warp-level fence suffices

        // O += P @ V
#pragma unroll
        for (int k0c = 0; k0c < 8; k0c++) {
            const int k0 = k0c * 8;
            uint32_t af[2][4];
#pragma unroll
            for (int mt = 0; mt < 2; mt++) {
                const int row = wm * 32 + mt * 16 + (lane >> 2);
                af[mt][0] = Ps[row * 68 + k0 + (lane & 3)];
                af[mt][1] = Ps[(row + 8) * 68 + k0 + (lane & 3)];
                af[mt][2] = Ps[row * 68 + k0 + 4 + (lane & 3)];
                af[mt][3] = Ps[(row + 8) * 68 + k0 + 4 + (lane & 3)];
            }
            uint32_t bf[8][2];
#pragma unroll
            for (int nt = 0; nt < 8; nt++) {
                const int col = nt * 8 + (lane >> 2);
                bf[nt][0] = Vs[(k0 + (lane & 3)) * 68 + col];
                bf[nt][1] = Vs[(k0 + 4 + (lane & 3)) * 68 + col];
            }
#pragma unroll
            for (int mt = 0; mt < 2; mt++)
#pragma unroll
                for (int nt = 0; nt < 8; nt++)
                    mma_tf32(o[mt][nt], af[mt], bf[nt]);
        }
        // next iteration's top barrier orders all buffer reuse
    }

    // epilogue: normalize, tf32-round, write g_obuf[b][s][d]
#pragma unroll
    for (int mt = 0; mt < 2; mt++)
#pragma unroll
        for (int half = 0; half < 2; half++) {
            const int rid = mt * 2 + half;
            const float inv = 1.0f / l_run[rid];
            const int row = qt * 128 + wm * 32 + mt * 16 + (lane >> 2) + 8 * half;
#pragma unroll
            for (int nt = 0; nt < 8; nt++) {
                const int d = h * 64 + nt * 8 + 2 * (lane & 3);
                uint2 u;
                u.x = f2tf(o[mt][nt][2 * half] * inv);
                u.y = f2tf(o[mt][nt][2 * half + 1] * inv);
                *(uint2*)&g_obuf[((size_t)b * SS + row) * DD + d] = u;
            }
        }
}

#define ATTN_SMEM ((4 * 4352 + 128 * 68) * 4)

// ---------------------------------------------------------------------------
extern "C" void kernel_launch(void* const* d_in, const int* in_sizes, int n_in,
                              void* d_out, int out_size) {
    const float* x   = (const float*)d_in[0];  // (4, 2048, 768)
    const float* wqk = (const float*)d_in[1];  // (3, 768, 768)
    const float* wo  = (const float*)d_in[2];  // (768, 768)
    float* out = (float*)d_out;                // (4, 2048, 768)
    (void)in_sizes; (void)n_in; (void)out_size;

    float *xr, *wqkvr, *wor, *obuf;
    cudaGetSymbolAddress((void**)&xr, g_xr);
    cudaGetSymbolAddress((void**)&wqkvr, g_wqkvr);
    cudaGetSymbolAddress((void**)&wor, g_wor);
    cudaGetSymbolAddress((void**)&obuf, g_obuf);

    cudaFuncSetAttribute(gemm_tf32<1>, cudaFuncAttributeMaxDynamicSharedMemorySize, GEMM_SMEM);
    cudaFuncSetAttribute(gemm_tf32<0>, cudaFuncAttributeMaxDynamicSharedMemorySize, GEMM_SMEM);
    cudaFuncSetAttribute(attn_tc, cudaFuncAttributeMaxDynamicSharedMemorySize, ATTN_SMEM);

    // 0) pre-round inputs/weights to tf32
    {
        int n4x = MTOT * DD / 4, n4q = NQKV * DD / 4, n4o = DD * DD / 4;
        preround<<<(n4x + 255) / 256, 256>>>(xr, x, n4x);
        preround<<<(n4q + 255) / 256, 256>>>(wqkvr, wqk, n4q);
        preround<<<(n4o + 255) / 256, 256>>>(wor, wo, n4o);
    }

    // 1) QKV projection -> g_qkv (remapped, rounded)
    gemm_tf32<1><<<dim3(NQKV / 128, MTOT / 256), 256, GEMM_SMEM>>>(xr, wqkvr, nullptr, MTOT, NQKV, DD);

    // 2) Causal attention -> g_obuf (rounded)
    attn_tc<<<dim3(SS / 128, HH, BB), 128, ATTN_SMEM>>>();

    // 3) O projection -> out
    gemm_tf32<0><<<dim3(DD / 128, MTOT / 256), 256, GEMM_SMEM>>>(obuf, wor, out, MTOT, DD, DD);
}

// round 9
// speedup vs baseline: 1.0566x; 1.0566x over previous
#include <cuda_runtime.h>
#include <math.h>
#include <stdint.h>

#define BB 4
#define SS 2048
#define DD 768
#define HH 12
#define DKK 64
#define MTOT (BB*SS)   // 8192
#define NQKV (3*DD)    // 2304

// Scratch (all values stored as tf32-rounded fp32 bit patterns)
__device__ float g_qkv[(size_t)3 * BB * HH * SS * DKK];
__device__ float g_obuf[(size_t)BB * SS * DD];
__device__ float g_xr[(size_t)MTOT * DD];
__device__ float g_wqkvr[(size_t)NQKV * DD];
__device__ float g_wor[(size_t)DD * DD];

// ---------------------------------------------------------------------------
// helpers
// ---------------------------------------------------------------------------
__device__ __forceinline__ uint32_t f2tf(float x) {
    uint32_t r;
    asm("cvt.rna.tf32.f32 %0, %1;" : "=r"(r) : "f"(x));
    return r;
}

__device__ __forceinline__ void mma_tf32(float* c, const uint32_t* a, const uint32_t* b) {
    asm volatile(
        "mma.sync.aligned.m16n8k8.row.col.f32.tf32.tf32.f32 "
        "{%0,%1,%2,%3}, {%4,%5,%6,%7}, {%8,%9}, {%0,%1,%2,%3};\n"
        : "+f"(c[0]), "+f"(c[1]), "+f"(c[2]), "+f"(c[3])
        : "r"(a[0]), "r"(a[1]), "r"(a[2]), "r"(a[3]), "r"(b[0]), "r"(b[1]));
}

__device__ __forceinline__ void cp_async16(void* smem, const void* gmem) {
    uint32_t s = (uint32_t)__cvta_generic_to_shared(smem);
    asm volatile("cp.async.cg.shared.global [%0], [%1], 16;\n" :: "r"(s), "l"(gmem));
}
__device__ __forceinline__ void cp_commit() { asm volatile("cp.async.commit_group;\n"); }
template <int N>
__device__ __forceinline__ void cp_wait() { asm volatile("cp.async.wait_group %0;\n" :: "n"(N)); }

// fast 2^x on the FMA/ALU pipes (no MUFU). fexp2(0) == 1.0f exactly.
__device__ __forceinline__ float fexp2(float x) {
    x = fmaxf(x, -120.0f);
    float z = x + 12582912.0f;
    float f = x - (z - 12582912.0f);
    int   i = __float_as_int(z) - 0x4B400000;
    float p = 0.0096818f;
    p = fmaf(p, f, 0.0555041f);
    p = fmaf(p, f, 0.2402265f);
    p = fmaf(p, f, 0.6931472f);
    p = fmaf(p, f, 1.0f);
    return __int_as_float(__float_as_int(p) + (i << 23));
}

#define CEXP 0.1803368801111204f   /* log2(e)/sqrt(64) */
#define NEGINF __int_as_float(0xff800000)

// ---------------------------------------------------------------------------
// tf32 pre-rounding pass
// ---------------------------------------------------------------------------
__global__ void preround(float* __restrict__ dst, const float* __restrict__ src, int n4) {
    int i = blockIdx.x * blockDim.x + threadIdx.x;
    if (i < n4) {
        float4 v = ((const float4*)src)[i];
        uint4 u;
        u.x = f2tf(v.x); u.y = f2tf(v.y); u.z = f2tf(v.z); u.w = f2tf(v.w);
        ((uint4*)dst)[i] = u;
    }
}

// ---------------------------------------------------------------------------
// tf32 tensor-core GEMM on PRE-ROUNDED inputs: C = A(M,K) @ W(N,K)^T.
// BM=256, BN=128, BK=16; 8 warps (4x2), warp 64x64. 3-stage cp.async.
// ---------------------------------------------------------------------------
#define GSTAGES 3
#define GASLOT (256 * 20)
#define GBSLOT (128 * 20)
#define GEMM_SMEM (GSTAGES * (GASLOT + GBSLOT) * 4)

template <int REMAP>
__global__ __launch_bounds__(256, 1) void gemm_tf32(const float* __restrict__ A,
                                                    const float* __restrict__ W,
                                                    float* __restrict__ C,
                                                    int M, int N, int K) {
    extern __shared__ uint32_t gsm[];
    uint32_t* As = gsm;
    uint32_t* Bs = gsm + GSTAGES * GASLOT;

    const int tid  = threadIdx.x;
    const int lane = tid & 31;
    const int wid  = tid >> 5;
    const int wm   = wid >> 1;
    const int wn   = wid & 1;
    const int m0   = blockIdx.y * 256;
    const int n0   = blockIdx.x * 128;

    const int r0 = tid >> 2;
    const int kv = (tid & 3) << 2;

    const int NT = K / 16;

    const float* Abase = A + (size_t)(m0 + r0) * K + kv;
    const float* Wbase = W + (size_t)(n0 + r0) * K + kv;

    float c[4][8][4];
#pragma unroll
    for (int mt = 0; mt < 4; mt++)
#pragma unroll
        for (int nt = 0; nt < 8; nt++)
#pragma unroll
            for (int j = 0; j < 4; j++) c[mt][nt][j] = 0.0f;

#pragma unroll
    for (int s = 0; s < GSTAGES - 1; s++) {
        uint32_t* as = As + s * GASLOT;
        uint32_t* bs = Bs + s * GBSLOT;
        const float* ap = Abase + s * 16;
        const float* wp = Wbase + s * 16;
#pragma unroll
        for (int rr = 0; rr < 4; rr++)
            cp_async16(&as[(r0 + rr * 64) * 20 + kv], ap + (size_t)(rr * 64) * K);
        cp_async16(&bs[r0 * 20 + kv], wp);
        cp_async16(&bs[(r0 + 64) * 20 + kv], wp + (size_t)64 * K);
        cp_commit();
    }

    for (int kt = 0; kt < NT; kt++) {
        cp_wait<GSTAGES - 2>();
        __syncthreads();

        if (kt + GSTAGES - 1 < NT) {
            const int slot = (kt + GSTAGES - 1) % GSTAGES;
            uint32_t* as = As + slot * GASLOT;
            uint32_t* bs = Bs + slot * GBSLOT;
            const float* ap = Abase + (size_t)(kt + GSTAGES - 1) * 16;
            const float* wp = Wbase + (size_t)(kt + GSTAGES - 1) * 16;
#pragma unroll
            for (int rr = 0; rr < 4; rr++)
                cp_async16(&as[(r0 + rr * 64) * 20 + kv], ap + (size_t)(rr * 64) * K);
            cp_async16(&bs[r0 * 20 + kv], wp);
            cp_async16(&bs[(r0 + 64) * 20 + kv], wp + (size_t)64 * K);
        }
        cp_commit();

        const uint32_t* as = As + (kt % GSTAGES) * GASLOT;
        const uint32_t* bs = Bs + (kt % GSTAGES) * GBSLOT;

#pragma unroll
        for (int k0 = 0; k0 < 16; k0 += 8) {
            uint32_t af[4][4];
#pragma unroll
            for (int mt = 0; mt < 4; mt++) {
                const int row = wm * 64 + mt * 16 + (lane >> 2);
                af[mt][0] = as[row * 20 + k0 + (lane & 3)];
                af[mt][1] = as[(row + 8) * 20 + k0 + (lane & 3)];
                af[mt][2] = as[row * 20 + k0 + 4 + (lane & 3)];
                af[mt][3] = as[(row + 8) * 20 + k0 + 4 + (lane & 3)];
            }
            uint32_t bf[8][2];
#pragma unroll
            for (int nt = 0; nt < 8; nt++) {
                const int col = wn * 64 + nt * 8 + (lane >> 2);
                bf[nt][0] = bs[col * 20 + k0 + (lane & 3)];
                bf[nt][1] = bs[col * 20 + k0 + 4 + (lane & 3)];
            }
#pragma unroll
            for (int mt = 0; mt < 4; mt++)
#pragma unroll
                for (int nt = 0; nt < 8; nt++)
                    mma_tf32(c[mt][nt], af[mt], bf[nt]);
        }
    }

    // epilogue
#pragma unroll
    for (int mt = 0; mt < 4; mt++) {
#pragma unroll
        for (int half = 0; half < 2; half++) {
            const int m = m0 + wm * 64 + mt * 16 + (lane >> 2) + half * 8;
#pragma unroll
            for (int nt = 0; nt < 8; nt++) {
                const int n = n0 + wn * 64 + nt * 8 + 2 * (lane & 3);
                const float v0 = c[mt][nt][2 * half + 0];
                const float v1 = c[mt][nt][2 * half + 1];
                if (REMAP) {
                    // n,n+1 are consecutive dk within one head -> float2 store
                    const int t = (n >= 2 * DD) ? 2 : ((n >= DD) ? 1 : 0);
                    const int r = n - t * DD;
                    const int hh = r >> 6;
                    const int e = r & 63;
                    const int bb = m >> 11;
                    const int ss = m & 2047;
                    size_t idx = ((((size_t)t * BB + bb) * HH + hh) * SS + ss) * DKK + e;
                    uint2 u;
                    u.x = f2tf(v0);
                    u.y = f2tf(v1);
                    *(uint2*)&g_qkv[idx] = u;
                } else {
                    float2 v = make_float2(v0, v1);
                    *(float2*)&C[(size_t)m * N + n] = v;
                }
            }
        }
    }
}

// ---------------------------------------------------------------------------
// Tensor-core causal flash attention (R6 structure). Br=128, Bc=64, dk=64.
// 128 threads = 4 warps; warp tile 32x64. Rescale-skip when running max is
// unchanged (bit-identical: fexp2(0)==1.0f).
// smem: Qs 128x68 + Ks 64x68 + Vs 64x68 + Ps 128x68 = 104448 B -> 2 CTAs/SM.
// ---------------------------------------------------------------------------
__global__ __launch_bounds__(128, 2) void attn_tc() {
    extern __shared__ uint32_t smx[];
    uint32_t* Qs = smx;                        // [128][68]
    uint32_t* Ks = smx + 128 * 68;             // [64][68]
    uint32_t* Vs = smx + 192 * 68;             // [64][68]
    uint32_t* Ps = smx + 256 * 68;             // [128][68]

    const int qt = (SS / 128 - 1) - blockIdx.x;   // largest work first
    const int h  = blockIdx.y;
    const int b  = blockIdx.z;
    const int tid  = threadIdx.x;
    const int lane = tid & 31;
    const int wm   = tid >> 5;   // 0..3

    const size_t plane = (size_t)BB * HH * SS * DKK;
    const size_t bh = (size_t)b * HH + h;
    const float* Qg = g_qkv + 0 * plane + bh * SS * DKK;
    const float* Kg = g_qkv + 1 * plane + bh * SS * DKK;
    const float* Vg = g_qkv + 2 * plane + bh * SS * DKK;

    const int lrow = tid >> 4;           // 0..7
    const int lc4  = (tid & 15) << 2;

#pragma unroll
    for (int i = 0; i < 16; i++) {
        const int row = lrow + i * 8;
        cp_async16(&Qs[row * 68 + lc4], Qg + ((size_t)(qt * 128 + row) << 6) + lc4);
    }
    cp_commit();
#pragma unroll
    for (int i = 0; i < 8; i++) {
        const int row = lrow + i * 8;
        cp_async16(&Ks[row * 68 + lc4], Kg + ((size_t)row << 6) + lc4);
    }
    cp_commit();
#pragma unroll
    for (int i = 0; i < 8; i++) {
        const int row = lrow + i * 8;
        cp_async16(&Vs[row * 68 + lc4], Vg + ((size_t)row << 6) + lc4);
    }
    cp_commit();

    float m_run[4], l_run[4], o[2][8][4];
#pragma unroll
    for (int r = 0; r < 4; r++) { m_run[r] = NEGINF; l_run[r] = 0.0f; }
#pragma unroll
    for (int mt = 0; mt < 2; mt++)
#pragma unroll
        for (int nt = 0; nt < 8; nt++)
#pragma unroll
            for (int j = 0; j < 4; j++) o[mt][nt][j] = 0.0f;

    const int ktmax = 2 * qt + 1;
    for (int kt = 0; kt <= ktmax; kt++) {
        cp_wait<1>();
        __syncthreads();

        float s[2][8][4];
#pragma unroll
        for (int mt = 0; mt < 2; mt++)
#pragma unroll
            for (int nt = 0; nt < 8; nt++)
#pragma unroll
                for (int j = 0; j < 4; j++) s[mt][nt][j] = 0.0f;

#pragma unroll
        for (int k0 = 0; k0 < 64; k0 += 8) {
            uint32_t af[2][4];
#pragma unroll
            for (int mt = 0; mt < 2; mt++) {
                const int row = wm * 32 + mt * 16 + (lane >> 2);
                af[mt][0] = Qs[row * 68 + k0 + (lane & 3)];
                af[mt][1] = Qs[(row + 8) * 68 + k0 + (lane & 3)];
                af[mt][2] = Qs[row * 68 + k0 + 4 + (lane & 3)];
                af[mt][3] = Qs[(row + 8) * 68 + k0 + 4 + (lane & 3)];
            }
            uint32_t bf[8][2];
#pragma unroll
            for (int nt = 0; nt < 8; nt++) {
                const int col = nt * 8 + (lane >> 2);
                bf[nt][0] = Ks[col * 68 + k0 + (lane & 3)];
                bf[nt][1] = Ks[col * 68 + k0 + 4 + (lane & 3)];
            }
#pragma unroll
            for (int mt = 0; mt < 2; mt++)
#pragma unroll
                for (int nt = 0; nt < 8; nt++)
                    mma_tf32(s[mt][nt], af[mt], bf[nt]);
        }

        if (kt >= 2 * qt) {
#pragma unroll
            for (int mt = 0; mt < 2; mt++)
#pragma unroll
                for (int cc = 0; cc < 4; cc++) {
                    const int row_g = qt * 128 + wm * 32 + mt * 16 + (lane >> 2) + 8 * (cc >> 1);
#pragma unroll
                    for (int nt = 0; nt < 8; nt++) {
                        const int col_g = kt * 64 + nt * 8 + 2 * (lane & 3) + (cc & 1);
                        if (col_g > row_g) s[mt][nt][cc] = NEGINF;
                    }
                }
        }

        // online softmax with rescale-skip
#pragma unroll
        for (int mt = 0; mt < 2; mt++)
#pragma unroll
            for (int half = 0; half < 2; half++) {
                const int rid = mt * 2 + half;
                float mv = NEGINF;
#pragma unroll
                for (int nt = 0; nt < 8; nt++)
                    mv = fmaxf(mv, fmaxf(s[mt][nt][2 * half], s[mt][nt][2 * half + 1]));
                mv = fmaxf(mv, __shfl_xor_sync(0xffffffffu, mv, 1));
                mv = fmaxf(mv, __shfl_xor_sync(0xffffffffu, mv, 2));
                const float mn = fmaxf(m_run[rid], mv);
                const bool same = (mn == m_run[rid]);   // sc would be exactly 1
                float rs = 0.0f;
#pragma unroll
                for (int nt = 0; nt < 8; nt++)
#pragma unroll
                    for (int j = 0; j < 2; j++) {
                        float p = fexp2((s[mt][nt][2 * half + j] - mn) * CEXP);
                        s[mt][nt][2 * half + j] = p;
                        rs += p;
                    }
                rs += __shfl_xor_sync(0xffffffffu, rs, 1);
                rs += __shfl_xor_sync(0xffffffffu, rs, 2);
                if (same) {
                    l_run[rid] += rs;
                } else {
                    const float sc = fexp2((m_run[rid] - mn) * CEXP);
                    m_run[rid] = mn;
                    l_run[rid] = l_run[rid] * sc + rs;
#pragma unroll
                    for (int nt = 0; nt < 8; nt++)
#pragma unroll
                        for (int j = 0; j < 2; j++) o[mt][nt][2 * half + j] *= sc;
                }
            }

#pragma unroll
        for (int mt = 0; mt < 2; mt++)
#pragma unroll
            for (int half = 0; half < 2; half++) {
                const int row = wm * 32 + mt * 16 + (lane >> 2) + 8 * half;
#pragma unroll
                for (int nt = 0; nt < 8; nt++) {
                    const int col = nt * 8 + 2 * (lane & 3);
                    uint2 u;
                    u.x = f2tf(s[mt][nt][2 * half]);
                    u.y = f2tf(s[mt][nt][2 * half + 1]);
                    *(uint2*)&Ps[row * 68 + col] = u;
                }
            }
        __syncthreads();

        if (kt < ktmax) {
#pragma unroll
            for (int i = 0; i < 8; i++) {
                const int row = lrow + i * 8;
                cp_async16(&Ks[row * 68 + lc4],
                           Kg + ((size_t)((kt + 1) * 64 + row) << 6) + lc4);
            }
        }
        cp_commit();

        cp_wait<1>();
        __syncthreads();

#pragma unroll
        for (int k0 = 0; k0 < 64; k0 += 8) {
            uint32_t af[2][4];
#pragma unroll
            for (int mt = 0; mt < 2; mt++) {
                const int row = wm * 32 + mt * 16 + (lane >> 2);
                af[mt][0] = Ps[row * 68 + k0 + (lane & 3)];
                af[mt][1] = Ps[(row + 8) * 68 + k0 + (lane & 3)];
                af[mt][2] = Ps[row * 68 + k0 + 4 + (lane & 3)];
                af[mt][3] = Ps[(row + 8) * 68 + k0 + 4 + (lane & 3)];
            }
            uint32_t bf[8][2];
#pragma unroll
            for (int nt = 0; nt < 8; nt++) {
                const int col = nt * 8 + (lane >> 2);
                bf[nt][0] = Vs[(k0 + (lane & 3)) * 68 + col];
                bf[nt][1] = Vs[(k0 + 4 + (lane & 3)) * 68 + col];
            }
#pragma unroll
            for (int mt = 0; mt < 2; mt++)
#pragma unroll
                for (int nt = 0; nt < 8; nt++)
                    mma_tf32(o[mt][nt], af[mt], bf[nt]);
        }
        __syncthreads();

        if (kt < ktmax) {
#pragma unroll
            for (int i = 0; i < 8; i++) {
                const int row = lrow + i * 8;
                cp_async16(&Vs[row * 68 + lc4],
                           Vg + ((size_t)((kt + 1) * 64 + row) << 6) + lc4);
            }
        }
        cp_commit();
    }

    // epilogue: normalize, tf32-round, write g_obuf[b][s][d]
#pragma unroll
    for (int mt = 0; mt < 2; mt++)
#pragma unroll
        for (int half = 0; half < 2; half++) {
            const int rid = mt * 2 + half;
            const float inv = 1.0f / l_run[rid];
            const int row = qt * 128 + wm * 32 + mt * 16 + (lane >> 2) + 8 * half;
#pragma unroll
            for (int nt = 0; nt < 8; nt++) {
                const int d = h * 64 + nt * 8 + 2 * (lane & 3);
                uint2 u;
                u.x = f2tf(o[mt][nt][2 * half] * inv);
                u.y = f2tf(o[mt][nt][2 * half + 1] * inv);
                *(uint2*)&g_obuf[((size_t)b * SS + row) * DD + d] = u;
            }
        }
}

#define ATTN_SMEM (384 * 68 * 4)

// ---------------------------------------------------------------------------
extern "C" void kernel_launch(void* const* d_in, const int* in_sizes, int n_in,
                              void* d_out, int out_size) {
    const float* x   = (const float*)d_in[0];  // (4, 2048, 768)
    const float* wqk = (const float*)d_in[1];  // (3, 768, 768)
    const float* wo  = (const float*)d_in[2];  // (768, 768)
    float* out = (float*)d_out;                // (4, 2048, 768)
    (void)in_sizes; (void)n_in; (void)out_size;

    float *xr, *wqkvr, *wor, *obuf;
    cudaGetSymbolAddress((void**)&xr, g_xr);
    cudaGetSymbolAddress((void**)&wqkvr, g_wqkvr);
    cudaGetSymbolAddress((void**)&wor, g_wor);
    cudaGetSymbolAddress((void**)&obuf, g_obuf);

    cudaFuncSetAttribute(gemm_tf32<1>, cudaFuncAttributeMaxDynamicSharedMemorySize, GEMM_SMEM);
    cudaFuncSetAttribute(gemm_tf32<0>, cudaFuncAttributeMaxDynamicSharedMemorySize, GEMM_SMEM);
    cudaFuncSetAttribute(attn_tc, cudaFuncAttributeMaxDynamicSharedMemorySize, ATTN_SMEM);

    // 0) pre-round inputs/weights to tf32
    {
        int n4x = MTOT * DD / 4, n4q = NQKV * DD / 4, n4o = DD * DD / 4;
        preround<<<(n4x + 255) / 256, 256>>>(xr, x, n4x);
        preround<<<(n4q + 255) / 256, 256>>>(wqkvr, wqk, n4q);
        preround<<<(n4o + 255) / 256, 256>>>(wor, wo, n4o);
    }

    // 1) QKV projection -> g_qkv (remapped, rounded)
    gemm_tf32<1><<<dim3(NQKV / 128, MTOT / 256), 256, GEMM_SMEM>>>(xr, wqkvr, nullptr, MTOT, NQKV, DD);

    // 2) Causal attention -> g_obuf (rounded)
    attn_tc<<<dim3(SS / 128, HH, BB), 128, ATTN_SMEM>>>();

    // 3) O projection -> out
    gemm_tf32<0><<<dim3(DD / 128, MTOT / 256), 256, GEMM_SMEM>>>(obuf, wor, out, MTOT, DD, DD);
}